// round 1
// baseline (speedup 1.0000x reference)
#include <cuda_runtime.h>
#include <math.h>

#define NN 3072
#define CA 128
#define CS 384
#define CZ 16
#define NH 4
#define DH 32
#define CF 256          // NEXP * CA
#define LNEPS 1e-5f

// ---------------- scratch (device globals; no allocation allowed) ----------------
static __device__ float g_an[NN*CA];   // LN(a)
static __device__ float g_sn[NN*CS];   // LN(s) raw (no s_w)
static __device__ float g_h[NN*CA];    // adaln1 output
static __device__ float g_q[NN*CA];    // q pre-scaled by 1/sqrt(D)
static __device__ float g_k[NN*CA];
static __device__ float g_v[NN*CA];
static __device__ float g_g[NN*CA];    // sigmoid(h@wg)
static __device__ float g_o[NN*CA];    // attention output (pre-gate)
static __device__ float g_r1[NN*CA];   // residual 1 (attn_out)
static __device__ float g_an2[NN*CA];  // LN(attn_out)
static __device__ float g_h2[NN*CA];   // adaln2 output

__device__ __forceinline__ float sigmoidf_(float x) { return 1.f / (1.f + __expf(-x)); }

// ---------------- block reduce (128 threads) ----------------
__device__ __forceinline__ float blockReduceSum128(float v, float* sh) {
    #pragma unroll
    for (int o = 16; o > 0; o >>= 1) v += __shfl_xor_sync(0xffffffffu, v, o);
    __syncthreads();                        // protect sh from previous use
    if ((threadIdx.x & 31) == 0) sh[threadIdx.x >> 5] = v;
    __syncthreads();
    return sh[0] + sh[1] + sh[2] + sh[3];
}

// ---------------- LN (no affine), one row per block, 128 threads ----------------
template <int C>
__global__ void ln_kernel(const float* __restrict__ in, float* __restrict__ out) {
    __shared__ float sh[4];
    constexpr int PT = C / 128;
    int r = blockIdx.x;
    const float* row = in + (size_t)r * C;
    float v[PT];
    float lsum = 0.f;
    #pragma unroll
    for (int i = 0; i < PT; i++) { v[i] = row[threadIdx.x + i * 128]; lsum += v[i]; }
    float mean = blockReduceSum128(lsum, sh) * (1.f / (float)C);
    float lss = 0.f;
    #pragma unroll
    for (int i = 0; i < PT; i++) { float d = v[i] - mean; lss += d * d; }
    float var = blockReduceSum128(lss, sh) * (1.f / (float)C);
    float rs = rsqrtf(var + LNEPS);
    #pragma unroll
    for (int i = 0; i < PT; i++)
        out[(size_t)r * C + threadIdx.x + i * 128] = (v[i] - mean) * rs;
}

// ---------------- AdaLN: h = sigmoid(sn@scale_w + scale_b)*an + sn@shift_w ----------------
// sn here is raw LN(s); s_w folded into weights per-j. 8 rows/block, 128 threads.
__global__ void adaln_kernel(const float* __restrict__ an_arr,
                             const float* __restrict__ s_w,
                             const float* __restrict__ scale_w,
                             const float* __restrict__ scale_b,
                             const float* __restrict__ shift_w,
                             float* __restrict__ out) {
    __shared__ float sn_sh[8 * CS];
    int r0 = blockIdx.x * 8;
    int c = threadIdx.x;
    #pragma unroll
    for (int i = 0; i < 8 * CS / 128; i++) {
        int idx = c + i * 128;
        sn_sh[idx] = g_sn[(size_t)r0 * CS + idx];
    }
    __syncthreads();
    float a1[8], a2[8];
    #pragma unroll
    for (int rr = 0; rr < 8; rr++) { a1[rr] = 0.f; a2[rr] = 0.f; }
    for (int j = 0; j < CS; j++) {
        float sw = s_w[j];
        float w1 = scale_w[j * CA + c] * sw;
        float w2 = shift_w[j * CA + c] * sw;
        #pragma unroll
        for (int rr = 0; rr < 8; rr++) {
            float sv = sn_sh[rr * CS + j];
            a1[rr] = fmaf(sv, w1, a1[rr]);
            a2[rr] = fmaf(sv, w2, a2[rr]);
        }
    }
    float sb = scale_b[c];
    #pragma unroll
    for (int rr = 0; rr < 8; rr++) {
        float anv = an_arr[(size_t)(r0 + rr) * CA + c];
        out[(size_t)(r0 + rr) * CA + c] = sigmoidf_(a1[rr] + sb) * anv + a2[rr];
    }
}

// ---------------- QKVG projections from h. 8 rows/block, 128 threads ----------------
__global__ void qkvg_kernel(const float* __restrict__ wq, const float* __restrict__ bq,
                            const float* __restrict__ wk, const float* __restrict__ wv,
                            const float* __restrict__ wg) {
    __shared__ float h_sh[8 * CA];
    int r0 = blockIdx.x * 8;
    int c = threadIdx.x;
    #pragma unroll
    for (int i = 0; i < 8; i++) {
        int idx = c + i * 128;
        h_sh[idx] = g_h[(size_t)r0 * CA + idx];
    }
    __syncthreads();
    const float qscale = 0.17677669529663687f;  // 1/sqrt(32)
    // pass 1: q and g
    {
        float aq[8], ag[8];
        #pragma unroll
        for (int rr = 0; rr < 8; rr++) { aq[rr] = 0.f; ag[rr] = 0.f; }
        for (int j = 0; j < CA; j++) {
            float wqv = wq[j * CA + c];
            float wgv = wg[j * CA + c];
            #pragma unroll
            for (int rr = 0; rr < 8; rr++) {
                float hv = h_sh[rr * CA + j];
                aq[rr] = fmaf(hv, wqv, aq[rr]);
                ag[rr] = fmaf(hv, wgv, ag[rr]);
            }
        }
        float b = bq[c];
        #pragma unroll
        for (int rr = 0; rr < 8; rr++) {
            g_q[(size_t)(r0 + rr) * CA + c] = (aq[rr] + b) * qscale;
            g_g[(size_t)(r0 + rr) * CA + c] = sigmoidf_(ag[rr]);
        }
    }
    // pass 2: k and v
    {
        float ak[8], av[8];
        #pragma unroll
        for (int rr = 0; rr < 8; rr++) { ak[rr] = 0.f; av[rr] = 0.f; }
        for (int j = 0; j < CA; j++) {
            float wkv = wk[j * CA + c];
            float wvv = wv[j * CA + c];
            #pragma unroll
            for (int rr = 0; rr < 8; rr++) {
                float hv = h_sh[rr * CA + j];
                ak[rr] = fmaf(hv, wkv, ak[rr]);
                av[rr] = fmaf(hv, wvv, av[rr]);
            }
        }
        #pragma unroll
        for (int rr = 0; rr < 8; rr++) {
            g_k[(size_t)(r0 + rr) * CA + c] = ak[rr];
            g_v[(size_t)(r0 + rr) * CA + c] = av[rr];
        }
    }
}

// ---------------- Attention with fused pair-bias, flash-style ----------------
#define TQ 16
#define TK 32
#define KSTR 132   // padded row stride for q/k/v tiles (floats)
#define PSTR 36    // padded row stride for p/bias tiles (floats, mult of 4)

__global__ void attn_kernel(const float* __restrict__ z,
                            const float* __restrict__ lnzw,
                            const float* __restrict__ lnzb,
                            const float* __restrict__ wb) {
    extern __shared__ float sm[];
    float* q_sh = sm;                        // 16*132
    float* k_sh = q_sh + TQ * KSTR;          // 32*132
    float* v_sh = k_sh + TK * KSTR;          // 32*132
    float* p_sh = v_sh + TK * KSTR;          // 64*36
    float* b_sh = p_sh + TQ * NH * PSTR;     // 64*36
    __shared__ float cw[CZ], cb[CZ], cwb[CZ * NH];

    int tid = threadIdx.x;
    int q0 = blockIdx.x * TQ;
    if (tid < CZ) { cw[tid] = lnzw[tid]; cb[tid] = lnzb[tid]; }
    if (tid < CZ * NH) cwb[tid] = wb[tid];
    // preload Q tile (16 x 128)
    #pragma unroll
    for (int i = 0; i < 2; i++) {
        int idx = tid + i * 256;
        int row = idx >> 5, c4 = idx & 31;
        *(float4*)&q_sh[row * KSTR + c4 * 4] =
            *(const float4*)&g_q[(size_t)(q0 + row) * CA + c4 * 4];
    }
    __syncthreads();

    int warp = tid >> 5, lane = tid & 31;
    int h = warp & 3;
    int qbase = (warp >> 2) * 8;   // 0 or 8

    float m[8], l[8], oacc[8];
    #pragma unroll
    for (int i = 0; i < 8; i++) { m[i] = -1e30f; l[i] = 0.f; oacc[i] = 0.f; }

    for (int t = 0; t < NN / TK; t++) {
        int k0 = t * TK;
        __syncthreads();   // previous tile fully consumed
        // load K,V tiles (32 x 128 each)
        #pragma unroll
        for (int i = 0; i < 4; i++) {
            int idx = tid + i * 256;
            int row = idx >> 5, c4 = idx & 31;
            *(float4*)&k_sh[row * KSTR + c4 * 4] =
                *(const float4*)&g_k[(size_t)(k0 + row) * CA + c4 * 4];
            *(float4*)&v_sh[row * KSTR + c4 * 4] =
                *(const float4*)&g_v[(size_t)(k0 + row) * CA + c4 * 4];
        }
        // pair bias: 16x32 = 512 pairs, 2 per thread
        #pragma unroll
        for (int i = 0; i < 2; i++) {
            int p = tid + i * 256;
            int qq = p >> 5, kk = p & 31;
            const float* zp = z + ((size_t)(q0 + qq) * NN + (size_t)(k0 + kk)) * CZ;
            float zv[16];
            *(float4*)&zv[0]  = *(const float4*)&zp[0];
            *(float4*)&zv[4]  = *(const float4*)&zp[4];
            *(float4*)&zv[8]  = *(const float4*)&zp[8];
            *(float4*)&zv[12] = *(const float4*)&zp[12];
            float s = 0.f;
            #pragma unroll
            for (int j = 0; j < 16; j++) s += zv[j];
            float mean = s * (1.f / 16.f);
            float ss = 0.f;
            #pragma unroll
            for (int j = 0; j < 16; j++) { float d = zv[j] - mean; ss += d * d; }
            float rs = rsqrtf(ss * (1.f / 16.f) + LNEPS);
            float b0 = 0.f, b1 = 0.f, b2 = 0.f, b3 = 0.f;
            #pragma unroll
            for (int j = 0; j < 16; j++) {
                float nz = fmaf((zv[j] - mean) * rs, cw[j], cb[j]);
                b0 = fmaf(nz, cwb[j * 4 + 0], b0);
                b1 = fmaf(nz, cwb[j * 4 + 1], b1);
                b2 = fmaf(nz, cwb[j * 4 + 2], b2);
                b3 = fmaf(nz, cwb[j * 4 + 3], b3);
            }
            b_sh[(qq * 4 + 0) * PSTR + kk] = b0;
            b_sh[(qq * 4 + 1) * PSTR + kk] = b1;
            b_sh[(qq * 4 + 2) * PSTR + kk] = b2;
            b_sh[(qq * 4 + 3) * PSTR + kk] = b3;
        }
        __syncthreads();

        // logits: lane = k index, 8 q rows per warp, head h
        float lg[8];
        #pragma unroll
        for (int qi = 0; qi < 8; qi++)
            lg[qi] = b_sh[((qbase + qi) * 4 + h) * PSTR + lane];
        #pragma unroll
        for (int d4 = 0; d4 < 8; d4++) {
            float4 kv = *(float4*)&k_sh[lane * KSTR + h * DH + d4 * 4];
            #pragma unroll
            for (int qi = 0; qi < 8; qi++) {
                float4 qv = *(float4*)&q_sh[(qbase + qi) * KSTR + h * DH + d4 * 4];
                lg[qi] = fmaf(qv.x, kv.x, lg[qi]);
                lg[qi] = fmaf(qv.y, kv.y, lg[qi]);
                lg[qi] = fmaf(qv.z, kv.z, lg[qi]);
                lg[qi] = fmaf(qv.w, kv.w, lg[qi]);
            }
        }
        // online softmax per (q,h) row (reduction across lanes = k)
        float scl[8];
        #pragma unroll
        for (int qi = 0; qi < 8; qi++) {
            float mx = lg[qi];
            #pragma unroll
            for (int o = 16; o > 0; o >>= 1)
                mx = fmaxf(mx, __shfl_xor_sync(0xffffffffu, mx, o));
            float mn = fmaxf(m[qi], mx);
            float p = __expf(lg[qi] - mn);
            float sum = p;
            #pragma unroll
            for (int o = 16; o > 0; o >>= 1)
                sum += __shfl_xor_sync(0xffffffffu, sum, o);
            float sc = __expf(m[qi] - mn);
            l[qi] = l[qi] * sc + sum;
            m[qi] = mn;
            scl[qi] = sc;
            p_sh[((qbase + qi) * 4 + h) * PSTR + lane] = p;
        }
        __syncwarp();
        // O accumulation: lane = d index
        #pragma unroll
        for (int qi = 0; qi < 8; qi++) oacc[qi] *= scl[qi];
        #pragma unroll
        for (int k4 = 0; k4 < 8; k4++) {
            float vv0 = v_sh[(k4 * 4 + 0) * KSTR + h * DH + lane];
            float vv1 = v_sh[(k4 * 4 + 1) * KSTR + h * DH + lane];
            float vv2 = v_sh[(k4 * 4 + 2) * KSTR + h * DH + lane];
            float vv3 = v_sh[(k4 * 4 + 3) * KSTR + h * DH + lane];
            #pragma unroll
            for (int qi = 0; qi < 8; qi++) {
                float4 pv = *(float4*)&p_sh[((qbase + qi) * 4 + h) * PSTR + k4 * 4];
                oacc[qi] = fmaf(pv.x, vv0, oacc[qi]);
                oacc[qi] = fmaf(pv.y, vv1, oacc[qi]);
                oacc[qi] = fmaf(pv.z, vv2, oacc[qi]);
                oacc[qi] = fmaf(pv.w, vv3, oacc[qi]);
            }
        }
    }
    // write out (lane = d)
    #pragma unroll
    for (int qi = 0; qi < 8; qi++) {
        g_o[(size_t)(q0 + qbase + qi) * CA + h * DH + lane] = oacc[qi] / l[qi];
    }
}

// ---------------- output proj + style gate + residual 1 ----------------
__global__ void attnout_kernel(const float* __restrict__ wo,
                               const float* __restrict__ s,
                               const float* __restrict__ sg1w,
                               const float* __restrict__ sg1b,
                               const float* __restrict__ a) {
    __shared__ float go_sh[8 * CA];
    __shared__ float s_sh[8 * CS];
    int r0 = blockIdx.x * 8;
    int c = threadIdx.x;
    #pragma unroll
    for (int i = 0; i < 8; i++) {
        int idx = c + i * 128;
        go_sh[idx] = g_g[(size_t)r0 * CA + idx] * g_o[(size_t)r0 * CA + idx];
    }
    #pragma unroll
    for (int i = 0; i < 8 * CS / 128; i++) {
        int idx = c + i * 128;
        s_sh[idx] = s[(size_t)r0 * CS + idx];
    }
    __syncthreads();
    float aA[8];
    #pragma unroll
    for (int rr = 0; rr < 8; rr++) aA[rr] = 0.f;
    for (int j = 0; j < CA; j++) {
        float w = wo[j * CA + c];
        #pragma unroll
        for (int rr = 0; rr < 8; rr++) aA[rr] = fmaf(go_sh[rr * CA + j], w, aA[rr]);
    }
    float aG[8];
    #pragma unroll
    for (int rr = 0; rr < 8; rr++) aG[rr] = 0.f;
    for (int j = 0; j < CS; j++) {
        float w = sg1w[j * CA + c];
        #pragma unroll
        for (int rr = 0; rr < 8; rr++) aG[rr] = fmaf(s_sh[rr * CS + j], w, aG[rr]);
    }
    float gb = sg1b[c];
    #pragma unroll
    for (int rr = 0; rr < 8; rr++) {
        g_r1[(size_t)(r0 + rr) * CA + c] =
            sigmoidf_(aG[rr] + gb) * aA[rr] + a[(size_t)(r0 + rr) * CA + c];
    }
}

// ---------------- SwiGLU FFN + style gate + residual 2 ----------------
__global__ void ffn_kernel(const float* __restrict__ w1, const float* __restrict__ w2,
                           const float* __restrict__ wout,
                           const float* __restrict__ s,
                           const float* __restrict__ sg2w, const float* __restrict__ sg2b,
                           float* __restrict__ out) {
    __shared__ float h_sh[8 * CA];
    __shared__ float s_sh[8 * CS];
    __shared__ float gt_sh[8 * CF];
    int r0 = blockIdx.x * 8;
    int tid = threadIdx.x;   // 256 threads
    for (int i = tid; i < 8 * CA; i += 256) h_sh[i] = g_h2[(size_t)r0 * CA + i];
    for (int i = tid; i < 8 * CS; i += 256) s_sh[i] = s[(size_t)r0 * CS + i];
    __syncthreads();
    {
        int c = tid;  // 0..255 output channels of w1/w2
        float u1[8], u2[8];
        #pragma unroll
        for (int rr = 0; rr < 8; rr++) { u1[rr] = 0.f; u2[rr] = 0.f; }
        for (int j = 0; j < CA; j++) {
            float w1v = w1[j * CF + c];
            float w2v = w2[j * CF + c];
            #pragma unroll
            for (int rr = 0; rr < 8; rr++) {
                float hv = h_sh[rr * CA + j];
                u1[rr] = fmaf(hv, w1v, u1[rr]);
                u2[rr] = fmaf(hv, w2v, u2[rr]);
            }
        }
        #pragma unroll
        for (int rr = 0; rr < 8; rr++) {
            float x = u1[rr];
            gt_sh[rr * CF + c] = (x * sigmoidf_(x)) * u2[rr];
        }
    }
    __syncthreads();
    if (tid < 128) {
        int c = tid;
        float aF[8];
        #pragma unroll
        for (int rr = 0; rr < 8; rr++) aF[rr] = 0.f;
        for (int j = 0; j < CF; j++) {
            float w = wout[j * CA + c];
            #pragma unroll
            for (int rr = 0; rr < 8; rr++) aF[rr] = fmaf(gt_sh[rr * CF + j], w, aF[rr]);
        }
        float aG[8];
        #pragma unroll
        for (int rr = 0; rr < 8; rr++) aG[rr] = 0.f;
        for (int j = 0; j < CS; j++) {
            float w = sg2w[j * CA + c];
            #pragma unroll
            for (int rr = 0; rr < 8; rr++) aG[rr] = fmaf(s_sh[rr * CS + j], w, aG[rr]);
        }
        float gb = sg2b[c];
        #pragma unroll
        for (int rr = 0; rr < 8; rr++) {
            out[(size_t)(r0 + rr) * CA + c] =
                sigmoidf_(aG[rr] + gb) * aF[rr] + g_r1[(size_t)(r0 + rr) * CA + c];
        }
    }
}

// ---------------- launch ----------------
extern "C" void kernel_launch(void* const* d_in, const int* in_sizes, int n_in,
                              void* d_out, int out_size) {
    const float* a      = (const float*)d_in[0];
    const float* s      = (const float*)d_in[1];
    const float* z      = (const float*)d_in[2];
    const float* a1sw   = (const float*)d_in[3];
    const float* a1scw  = (const float*)d_in[4];
    const float* a1scb  = (const float*)d_in[5];
    const float* a1shw  = (const float*)d_in[6];
    const float* wq     = (const float*)d_in[7];
    const float* bq     = (const float*)d_in[8];
    const float* wk     = (const float*)d_in[9];
    const float* wv     = (const float*)d_in[10];
    const float* lnzw   = (const float*)d_in[11];
    const float* lnzb   = (const float*)d_in[12];
    const float* wb     = (const float*)d_in[13];
    const float* wg     = (const float*)d_in[14];
    const float* wo     = (const float*)d_in[15];
    const float* sg1w   = (const float*)d_in[16];
    const float* sg1b   = (const float*)d_in[17];
    const float* a2sw   = (const float*)d_in[18];
    const float* a2scw  = (const float*)d_in[19];
    const float* a2scb  = (const float*)d_in[20];
    const float* a2shw  = (const float*)d_in[21];
    const float* w1     = (const float*)d_in[22];
    const float* w2     = (const float*)d_in[23];
    const float* wout   = (const float*)d_in[24];
    const float* sg2w   = (const float*)d_in[25];
    const float* sg2b   = (const float*)d_in[26];
    float* out = (float*)d_out;

    const int ATTN_SMEM = (TQ * KSTR + 2 * TK * KSTR + 2 * TQ * NH * PSTR) * 4;
    cudaFuncSetAttribute(attn_kernel, cudaFuncAttributeMaxDynamicSharedMemorySize, ATTN_SMEM);

    // LN of a and s
    ln_kernel<CA><<<NN, 128>>>(a, g_an);
    ln_kernel<CS><<<NN, 128>>>(s, g_sn);
    // AdaLN 1 -> h
    adaln_kernel<<<NN / 8, 128>>>(g_an, a1sw, a1scw, a1scb, a1shw, g_h);
    // Q,K,V,G
    qkvg_kernel<<<NN / 8, 128>>>(wq, bq, wk, wv, wg);
    // attention with fused pair bias
    attn_kernel<<<NN / TQ, 256, ATTN_SMEM>>>(z, lnzw, lnzb, wb);
    // output projection + gate + residual 1
    attnout_kernel<<<NN / 8, 128>>>(wo, s, sg1w, sg1b, a);
    // LN of residual 1
    ln_kernel<CA><<<NN, 128>>>(g_r1, g_an2);
    // AdaLN 2 -> h2
    adaln_kernel<<<NN / 8, 128>>>(g_an2, a2sw, a2scw, a2scb, a2shw, g_h2);
    // SwiGLU FFN + gate + residual 2 -> out
    ffn_kernel<<<NN / 8, 256>>>(w1, w2, wout, s, sg2w, sg2b, out);
    (void)in_sizes; (void)n_in; (void)out_size;
}

// round 2
// speedup vs baseline: 1.1454x; 1.1454x over previous
#include <cuda_runtime.h>
#include <math.h>
#include <stdint.h>

#define NN 3072
#define CA 128
#define CS 384
#define CZ 16
#define NH 4
#define DH 32
#define CF 256
#define LNEPS 1e-5f

#define TQ 32
#define TK 32
#define NSPLIT 8
#define KPS (NN / NSPLIT)       // 384 keys per split
#define NT (KPS / TK)           // 12 tiles
#define KSTR 132
#define PSTR 36
#define ATHREADS 512

// ---------------- scratch ----------------
static __device__ float g_an[NN*CA];
static __device__ float g_sn[NN*CS];
static __device__ float g_h[NN*CA];
static __device__ float g_q[NN*CA];
static __device__ float g_k[NN*CA];
static __device__ float g_v[NN*CA];
static __device__ float g_g[NN*CA];
static __device__ float g_o[NN*CA];
static __device__ float g_r1[NN*CA];
static __device__ float g_an2[NN*CA];
static __device__ float g_h2[NN*CA];
static __device__ float g_po[(size_t)NSPLIT*NN*CA];
static __device__ float g_pm[NSPLIT*NN*NH];
static __device__ float g_pl[NSPLIT*NN*NH];

__device__ __forceinline__ float sigmoidf_(float x) { return 1.f / (1.f + __expf(-x)); }

__device__ __forceinline__ void cpa16(void* dst_smem, const void* src) {
    uint32_t d = (uint32_t)__cvta_generic_to_shared(dst_smem);
    asm volatile("cp.async.ca.shared.global [%0], [%1], 16;\n" :: "r"(d), "l"(src));
}
#define CPA_COMMIT() asm volatile("cp.async.commit_group;\n" ::: "memory")
#define CPA_WAIT0()  asm volatile("cp.async.wait_group 0;\n" ::: "memory")

// ---------------- LN (no affine), one row per block ----------------
__device__ __forceinline__ float blockReduceSum128(float v, float* sh) {
    #pragma unroll
    for (int o = 16; o > 0; o >>= 1) v += __shfl_xor_sync(0xffffffffu, v, o);
    __syncthreads();
    if ((threadIdx.x & 31) == 0) sh[threadIdx.x >> 5] = v;
    __syncthreads();
    return sh[0] + sh[1] + sh[2] + sh[3];
}

template <int C>
__global__ void ln_kernel(const float* __restrict__ in, float* __restrict__ out) {
    __shared__ float sh[4];
    constexpr int PT = C / 128;
    int r = blockIdx.x;
    const float* row = in + (size_t)r * C;
    float v[PT];
    float lsum = 0.f;
    #pragma unroll
    for (int i = 0; i < PT; i++) { v[i] = row[threadIdx.x + i * 128]; lsum += v[i]; }
    float mean = blockReduceSum128(lsum, sh) * (1.f / (float)C);
    float lss = 0.f;
    #pragma unroll
    for (int i = 0; i < PT; i++) { float d = v[i] - mean; lss += d * d; }
    float var = blockReduceSum128(lss, sh) * (1.f / (float)C);
    float rs = rsqrtf(var + LNEPS);
    #pragma unroll
    for (int i = 0; i < PT; i++)
        out[(size_t)r * C + threadIdx.x + i * 128] = (v[i] - mean) * rs;
}

// ---------------- AdaLN, 4 rows/block, 128 threads ----------------
__global__ void adaln_kernel(const float* __restrict__ an_arr,
                             const float* __restrict__ s_w,
                             const float* __restrict__ scale_w,
                             const float* __restrict__ scale_b,
                             const float* __restrict__ shift_w,
                             float* __restrict__ out) {
    __shared__ float sn_sh[4 * CS];
    int r0 = blockIdx.x * 4;
    int c = threadIdx.x;
    #pragma unroll
    for (int i = 0; i < 4 * CS / 128; i++) {
        int idx = c + i * 128;
        sn_sh[idx] = g_sn[(size_t)r0 * CS + idx] * s_w[idx % CS];
    }
    __syncthreads();
    float a1[4], a2[4];
    #pragma unroll
    for (int rr = 0; rr < 4; rr++) { a1[rr] = 0.f; a2[rr] = 0.f; }
    #pragma unroll 4
    for (int j = 0; j < CS; j++) {
        float w1 = scale_w[j * CA + c];
        float w2 = shift_w[j * CA + c];
        #pragma unroll
        for (int rr = 0; rr < 4; rr++) {
            float sv = sn_sh[rr * CS + j];
            a1[rr] = fmaf(sv, w1, a1[rr]);
            a2[rr] = fmaf(sv, w2, a2[rr]);
        }
    }
    float sb = scale_b[c];
    #pragma unroll
    for (int rr = 0; rr < 4; rr++) {
        float anv = an_arr[(size_t)(r0 + rr) * CA + c];
        out[(size_t)(r0 + rr) * CA + c] = sigmoidf_(a1[rr] + sb) * anv + a2[rr];
    }
}

// ---------------- QKVG, 4 rows/block, grid.y picks (q,g) or (k,v) ----------------
__global__ void qkvg_kernel(const float* __restrict__ wq, const float* __restrict__ bq,
                            const float* __restrict__ wk, const float* __restrict__ wv,
                            const float* __restrict__ wg) {
    __shared__ float h_sh[4 * CA];
    int r0 = blockIdx.x * 4;
    int c = threadIdx.x;
    #pragma unroll
    for (int i = 0; i < 4; i++) {
        int idx = c + i * 128;
        h_sh[idx] = g_h[(size_t)r0 * CA + idx];
    }
    __syncthreads();
    const float* wA = (blockIdx.y == 0) ? wq : wk;
    const float* wB = (blockIdx.y == 0) ? wg : wv;
    float aA[4], aB[4];
    #pragma unroll
    for (int rr = 0; rr < 4; rr++) { aA[rr] = 0.f; aB[rr] = 0.f; }
    #pragma unroll 8
    for (int j = 0; j < CA; j++) {
        float w1 = wA[j * CA + c];
        float w2 = wB[j * CA + c];
        #pragma unroll
        for (int rr = 0; rr < 4; rr++) {
            float hv = h_sh[rr * CA + j];
            aA[rr] = fmaf(hv, w1, aA[rr]);
            aB[rr] = fmaf(hv, w2, aB[rr]);
        }
    }
    if (blockIdx.y == 0) {
        const float qscale = 0.17677669529663687f;
        float b = bq[c];
        #pragma unroll
        for (int rr = 0; rr < 4; rr++) {
            g_q[(size_t)(r0 + rr) * CA + c] = (aA[rr] + b) * qscale;
            g_g[(size_t)(r0 + rr) * CA + c] = sigmoidf_(aB[rr]);
        }
    } else {
        #pragma unroll
        for (int rr = 0; rr < 4; rr++) {
            g_k[(size_t)(r0 + rr) * CA + c] = aA[rr];
            g_v[(size_t)(r0 + rr) * CA + c] = aB[rr];
        }
    }
}

// ---------------- Attention: split-K, cp.async pipelined ----------------
__global__ void __launch_bounds__(ATHREADS, 1)
attn_kernel(const float* __restrict__ z,
            const float* __restrict__ lnzw,
            const float* __restrict__ lnzb,
            const float* __restrict__ wb) {
    extern __shared__ float sm[];
    float* q_sh = sm;                           // TQ*KSTR = 4224
    float* k_sh = q_sh + TQ * KSTR;             // 2*TK*KSTR
    float* v_sh = k_sh + 2 * TK * KSTR;         // 2*TK*KSTR
    float* z_sh = v_sh + 2 * TK * KSTR;         // TQ*TK*16 = 16384
    float* b_sh = z_sh + TQ * TK * 16;          // TQ*NH*PSTR = 4608
    float* p_sh = b_sh + TQ * NH * PSTR;        // 4608
    __shared__ float cw[CZ], cb[CZ], cwb[CZ * NH];

    int tid = threadIdx.x;
    int q0 = blockIdx.x * TQ;
    int kbase = blockIdx.y * KPS;
    if (tid < CZ) { cw[tid] = lnzw[tid]; cb[tid] = lnzb[tid]; }
    if (tid < CZ * NH) cwb[tid] = wb[tid];

    // issue tile-0 async loads ASAP
    {
        int k0 = kbase;
        // z tile (1024 pairs x 16 floats), slot-swizzled
        #pragma unroll
        for (int pi = 0; pi < 2; pi++) {
            int p = tid + pi * 512;
            int qq = p >> 5, kk = p & 31, r = (p >> 1) & 3;
            const float* zp = z + ((size_t)(q0 + qq) * NN + (size_t)(k0 + kk)) * CZ;
            #pragma unroll
            for (int g = 0; g < 4; g++) {
                int slot = (g + r) & 3;
                cpa16(&z_sh[p * 16 + slot * 4], zp + g * 4);
            }
        }
        // K/V tile into buf 0
        #pragma unroll
        for (int i = 0; i < 2; i++) {
            int cch = tid + i * 512;
            int row = cch >> 5, c4 = cch & 31;
            cpa16(&k_sh[row * KSTR + c4 * 4], &g_k[(size_t)(k0 + row) * CA + c4 * 4]);
            cpa16(&v_sh[row * KSTR + c4 * 4], &g_v[(size_t)(k0 + row) * CA + c4 * 4]);
        }
    }
    CPA_COMMIT();

    // Q tile (regular loads)
    #pragma unroll
    for (int i = 0; i < 2; i++) {
        int cch = tid + i * 512;
        int row = cch >> 5, c4 = cch & 31;
        *(float4*)&q_sh[row * KSTR + c4 * 4] =
            *(const float4*)&g_q[(size_t)(q0 + row) * CA + c4 * 4];
    }

    int warp = tid >> 5, lane = tid & 31;
    int h = warp & 3;
    int qbase = (warp >> 2) * 8;   // 0,8,16,24

    float m[8], l[8], oacc[8];
    #pragma unroll
    for (int i = 0; i < 8; i++) { m[i] = -1e30f; l[i] = 0.f; oacc[i] = 0.f; }

    for (int t = 0; t < NT; t++) {
        CPA_WAIT0();
        __syncthreads();   // z(t), kv(t) visible; previous logits done

        // ---- pair bias from z_sh -> b_sh ----
        #pragma unroll
        for (int pi = 0; pi < 2; pi++) {
            int p = tid + pi * 512;
            int qq = p >> 5, kk = p & 31, r = (p >> 1) & 3;
            float zv[16];
            #pragma unroll
            for (int g = 0; g < 4; g++) {
                int slot = (g + r) & 3;
                float4 t4 = *(float4*)&z_sh[p * 16 + slot * 4];
                zv[g * 4 + 0] = t4.x; zv[g * 4 + 1] = t4.y;
                zv[g * 4 + 2] = t4.z; zv[g * 4 + 3] = t4.w;
            }
            float s = 0.f;
            #pragma unroll
            for (int j = 0; j < 16; j++) s += zv[j];
            float mean = s * (1.f / 16.f);
            float ss = 0.f;
            #pragma unroll
            for (int j = 0; j < 16; j++) { float d = zv[j] - mean; ss += d * d; }
            float rs = rsqrtf(ss * (1.f / 16.f) + LNEPS);
            float b0 = 0.f, b1 = 0.f, b2 = 0.f, b3 = 0.f;
            #pragma unroll
            for (int j = 0; j < 16; j++) {
                float nz = fmaf((zv[j] - mean) * rs, cw[j], cb[j]);
                b0 = fmaf(nz, cwb[j * 4 + 0], b0);
                b1 = fmaf(nz, cwb[j * 4 + 1], b1);
                b2 = fmaf(nz, cwb[j * 4 + 2], b2);
                b3 = fmaf(nz, cwb[j * 4 + 3], b3);
            }
            b_sh[(qq * 4 + 0) * PSTR + kk] = b0;
            b_sh[(qq * 4 + 1) * PSTR + kk] = b1;
            b_sh[(qq * 4 + 2) * PSTR + kk] = b2;
            b_sh[(qq * 4 + 3) * PSTR + kk] = b3;
        }
        __syncthreads();   // b_sh ready; z_sh free

        // ---- prefetch tile t+1 (overlaps with logits/PV below) ----
        if (t + 1 < NT) {
            int k0 = kbase + (t + 1) * TK;
            int buf = (t + 1) & 1;
            #pragma unroll
            for (int pi = 0; pi < 2; pi++) {
                int p = tid + pi * 512;
                int qq = p >> 5, kk = p & 31, r = (p >> 1) & 3;
                const float* zp = z + ((size_t)(q0 + qq) * NN + (size_t)(k0 + kk)) * CZ;
                #pragma unroll
                for (int g = 0; g < 4; g++) {
                    int slot = (g + r) & 3;
                    cpa16(&z_sh[p * 16 + slot * 4], zp + g * 4);
                }
            }
            #pragma unroll
            for (int i = 0; i < 2; i++) {
                int cch = tid + i * 512;
                int row = cch >> 5, c4 = cch & 31;
                cpa16(&k_sh[buf * TK * KSTR + row * KSTR + c4 * 4],
                      &g_k[(size_t)(k0 + row) * CA + c4 * 4]);
                cpa16(&v_sh[buf * TK * KSTR + row * KSTR + c4 * 4],
                      &g_v[(size_t)(k0 + row) * CA + c4 * 4]);
            }
        }
        CPA_COMMIT();

        const float* kbuf = k_sh + (t & 1) * TK * KSTR;
        const float* vbuf = v_sh + (t & 1) * TK * KSTR;

        // ---- logits: lane = k index ----
        float lg[8];
        #pragma unroll
        for (int qi = 0; qi < 8; qi++)
            lg[qi] = b_sh[((qbase + qi) * 4 + h) * PSTR + lane];
        #pragma unroll
        for (int d4 = 0; d4 < 8; d4++) {
            float4 kv = *(const float4*)&kbuf[lane * KSTR + h * DH + d4 * 4];
            #pragma unroll
            for (int qi = 0; qi < 8; qi++) {
                float4 qv = *(const float4*)&q_sh[(qbase + qi) * KSTR + h * DH + d4 * 4];
                lg[qi] = fmaf(qv.x, kv.x, lg[qi]);
                lg[qi] = fmaf(qv.y, kv.y, lg[qi]);
                lg[qi] = fmaf(qv.z, kv.z, lg[qi]);
                lg[qi] = fmaf(qv.w, kv.w, lg[qi]);
            }
        }
        // ---- online softmax ----
        float scl[8];
        #pragma unroll
        for (int qi = 0; qi < 8; qi++) {
            float mx = lg[qi];
            #pragma unroll
            for (int o = 16; o > 0; o >>= 1)
                mx = fmaxf(mx, __shfl_xor_sync(0xffffffffu, mx, o));
            float mn = fmaxf(m[qi], mx);
            float p = __expf(lg[qi] - mn);
            float sum = p;
            #pragma unroll
            for (int o = 16; o > 0; o >>= 1)
                sum += __shfl_xor_sync(0xffffffffu, sum, o);
            float sc = __expf(m[qi] - mn);
            l[qi] = l[qi] * sc + sum;
            m[qi] = mn;
            scl[qi] = sc;
            p_sh[((qbase + qi) * 4 + h) * PSTR + lane] = p;
        }
        __syncwarp();
        // ---- O accumulation: lane = d index ----
        #pragma unroll
        for (int qi = 0; qi < 8; qi++) oacc[qi] *= scl[qi];
        #pragma unroll
        for (int k4 = 0; k4 < 8; k4++) {
            float vv0 = vbuf[(k4 * 4 + 0) * KSTR + h * DH + lane];
            float vv1 = vbuf[(k4 * 4 + 1) * KSTR + h * DH + lane];
            float vv2 = vbuf[(k4 * 4 + 2) * KSTR + h * DH + lane];
            float vv3 = vbuf[(k4 * 4 + 3) * KSTR + h * DH + lane];
            #pragma unroll
            for (int qi = 0; qi < 8; qi++) {
                float4 pv = *(float4*)&p_sh[((qbase + qi) * 4 + h) * PSTR + k4 * 4];
                oacc[qi] = fmaf(pv.x, vv0, oacc[qi]);
                oacc[qi] = fmaf(pv.y, vv1, oacc[qi]);
                oacc[qi] = fmaf(pv.z, vv2, oacc[qi]);
                oacc[qi] = fmaf(pv.w, vv3, oacc[qi]);
            }
        }
    }
    // write partials (unnormalized o, plus m/l)
    size_t sp = blockIdx.y;
    #pragma unroll
    for (int qi = 0; qi < 8; qi++) {
        int q = q0 + qbase + qi;
        g_po[(sp * NN + q) * CA + h * DH + lane] = oacc[qi];
        if (lane == 0) {
            g_pm[(sp * NN + q) * NH + h] = m[qi];
            g_pl[(sp * NN + q) * NH + h] = l[qi];
        }
    }
}

// ---------------- split-K combine ----------------
__global__ void combine_kernel() {
    int tid = threadIdx.x;               // 256
    int q = blockIdx.x * 2 + (tid >> 7);
    int hd = tid & 127;
    int h = hd >> 5;
    float ms[NSPLIT];
    float M = -1e30f;
    #pragma unroll
    for (int s = 0; s < NSPLIT; s++) {
        ms[s] = g_pm[((size_t)s * NN + q) * NH + h];
        M = fmaxf(M, ms[s]);
    }
    float osum = 0.f, lsum = 0.f;
    #pragma unroll
    for (int s = 0; s < NSPLIT; s++) {
        float w = __expf(ms[s] - M);
        lsum = fmaf(w, g_pl[((size_t)s * NN + q) * NH + h], lsum);
        osum = fmaf(w, g_po[((size_t)s * NN + q) * CA + hd], osum);
    }
    g_o[(size_t)q * CA + hd] = osum / lsum;
}

// ---------------- output proj + style gate + residual 1, 4 rows/block ----------------
__global__ void attnout_kernel(const float* __restrict__ wo,
                               const float* __restrict__ s,
                               const float* __restrict__ sg1w,
                               const float* __restrict__ sg1b,
                               const float* __restrict__ a) {
    __shared__ float go_sh[4 * CA];
    __shared__ float s_sh[4 * CS];
    int r0 = blockIdx.x * 4;
    int c = threadIdx.x;
    #pragma unroll
    for (int i = 0; i < 4; i++) {
        int idx = c + i * 128;
        go_sh[idx] = g_g[(size_t)r0 * CA + idx] * g_o[(size_t)r0 * CA + idx];
    }
    #pragma unroll
    for (int i = 0; i < 4 * CS / 128; i++) {
        int idx = c + i * 128;
        s_sh[idx] = s[(size_t)r0 * CS + idx];
    }
    __syncthreads();
    float aA[4];
    #pragma unroll
    for (int rr = 0; rr < 4; rr++) aA[rr] = 0.f;
    #pragma unroll 8
    for (int j = 0; j < CA; j++) {
        float w = wo[j * CA + c];
        #pragma unroll
        for (int rr = 0; rr < 4; rr++) aA[rr] = fmaf(go_sh[rr * CA + j], w, aA[rr]);
    }
    float aG[4];
    #pragma unroll
    for (int rr = 0; rr < 4; rr++) aG[rr] = 0.f;
    #pragma unroll 4
    for (int j = 0; j < CS; j++) {
        float w = sg1w[j * CA + c];
        #pragma unroll
        for (int rr = 0; rr < 4; rr++) aG[rr] = fmaf(s_sh[rr * CS + j], w, aG[rr]);
    }
    float gb = sg1b[c];
    #pragma unroll
    for (int rr = 0; rr < 4; rr++) {
        g_r1[(size_t)(r0 + rr) * CA + c] =
            sigmoidf_(aG[rr] + gb) * aA[rr] + a[(size_t)(r0 + rr) * CA + c];
    }
}

// ---------------- SwiGLU FFN + gate + residual 2, 4 rows/block, 256 threads ----------------
__global__ void ffn_kernel(const float* __restrict__ w1, const float* __restrict__ w2,
                           const float* __restrict__ wout,
                           const float* __restrict__ s,
                           const float* __restrict__ sg2w, const float* __restrict__ sg2b,
                           float* __restrict__ out) {
    __shared__ float h_sh[4 * CA];
    __shared__ float s_sh[4 * CS];
    __shared__ float gt_sh[4 * CF];
    int r0 = blockIdx.x * 4;
    int tid = threadIdx.x;   // 256
    for (int i = tid; i < 4 * CA; i += 256) h_sh[i] = g_h2[(size_t)r0 * CA + i];
    for (int i = tid; i < 4 * CS; i += 256) s_sh[i] = s[(size_t)r0 * CS + i];
    __syncthreads();
    {
        int c = tid;
        float u1[4], u2[4];
        #pragma unroll
        for (int rr = 0; rr < 4; rr++) { u1[rr] = 0.f; u2[rr] = 0.f; }
        #pragma unroll 8
        for (int j = 0; j < CA; j++) {
            float w1v = w1[j * CF + c];
            float w2v = w2[j * CF + c];
            #pragma unroll
            for (int rr = 0; rr < 4; rr++) {
                float hv = h_sh[rr * CA + j];
                u1[rr] = fmaf(hv, w1v, u1[rr]);
                u2[rr] = fmaf(hv, w2v, u2[rr]);
            }
        }
        #pragma unroll
        for (int rr = 0; rr < 4; rr++) {
            float x = u1[rr];
            gt_sh[rr * CF + c] = (x * sigmoidf_(x)) * u2[rr];
        }
    }
    __syncthreads();
    {
        int c = tid & 127;
        int rrb = (tid >> 7) * 2;  // rows {0,1} or {2,3}
        float aF[2], aG[2];
        aF[0] = aF[1] = aG[0] = aG[1] = 0.f;
        #pragma unroll 8
        for (int j = 0; j < CF; j++) {
            float w = wout[j * CA + c];
            aF[0] = fmaf(gt_sh[(rrb + 0) * CF + j], w, aF[0]);
            aF[1] = fmaf(gt_sh[(rrb + 1) * CF + j], w, aF[1]);
        }
        #pragma unroll 4
        for (int j = 0; j < CS; j++) {
            float w = sg2w[j * CA + c];
            aG[0] = fmaf(s_sh[(rrb + 0) * CS + j], w, aG[0]);
            aG[1] = fmaf(s_sh[(rrb + 1) * CS + j], w, aG[1]);
        }
        float gb = sg2b[c];
        #pragma unroll
        for (int rr = 0; rr < 2; rr++) {
            out[(size_t)(r0 + rrb + rr) * CA + c] =
                sigmoidf_(aG[rr] + gb) * aF[rr] + g_r1[(size_t)(r0 + rrb + rr) * CA + c];
        }
    }
}

// ---------------- launch ----------------
extern "C" void kernel_launch(void* const* d_in, const int* in_sizes, int n_in,
                              void* d_out, int out_size) {
    const float* a      = (const float*)d_in[0];
    const float* s      = (const float*)d_in[1];
    const float* z      = (const float*)d_in[2];
    const float* a1sw   = (const float*)d_in[3];
    const float* a1scw  = (const float*)d_in[4];
    const float* a1scb  = (const float*)d_in[5];
    const float* a1shw  = (const float*)d_in[6];
    const float* wq     = (const float*)d_in[7];
    const float* bq     = (const float*)d_in[8];
    const float* wk     = (const float*)d_in[9];
    const float* wv     = (const float*)d_in[10];
    const float* lnzw   = (const float*)d_in[11];
    const float* lnzb   = (const float*)d_in[12];
    const float* wb     = (const float*)d_in[13];
    const float* wg     = (const float*)d_in[14];
    const float* wo     = (const float*)d_in[15];
    const float* sg1w   = (const float*)d_in[16];
    const float* sg1b   = (const float*)d_in[17];
    const float* a2sw   = (const float*)d_in[18];
    const float* a2scw  = (const float*)d_in[19];
    const float* a2scb  = (const float*)d_in[20];
    const float* a2shw  = (const float*)d_in[21];
    const float* w1     = (const float*)d_in[22];
    const float* w2     = (const float*)d_in[23];
    const float* wout   = (const float*)d_in[24];
    const float* sg2w   = (const float*)d_in[25];
    const float* sg2b   = (const float*)d_in[26];
    float* out = (float*)d_out;

    const int ATTN_SMEM =
        (TQ * KSTR + 4 * TK * KSTR + TQ * TK * 16 + 2 * TQ * NH * PSTR) * 4;
    static int attrset = 0;
    if (!attrset) {
        cudaFuncSetAttribute(attn_kernel, cudaFuncAttributeMaxDynamicSharedMemorySize, ATTN_SMEM);
        attrset = 1;
    }

    ln_kernel<CA><<<NN, 128>>>(a, g_an);
    ln_kernel<CS><<<NN, 128>>>(s, g_sn);
    adaln_kernel<<<NN / 4, 128>>>(g_an, a1sw, a1scw, a1scb, a1shw, g_h);
    qkvg_kernel<<<dim3(NN / 4, 2), 128>>>(wq, bq, wk, wv, wg);
    attn_kernel<<<dim3(NN / TQ, NSPLIT), ATHREADS, ATTN_SMEM>>>(z, lnzw, lnzb, wb);
    combine_kernel<<<NN / 2, 256>>>();
    attnout_kernel<<<NN / 4, 128>>>(wo, s, sg1w, sg1b, a);
    ln_kernel<CA><<<NN, 128>>>(g_r1, g_an2);
    adaln_kernel<<<NN / 4, 128>>>(g_an2, a2sw, a2scw, a2scb, a2shw, g_h2);
    ffn_kernel<<<NN / 4, 256>>>(w1, w2, wout, s, sg2w, sg2b, out);
    (void)in_sizes; (void)n_in; (void)out_size;
}